// round 6
// baseline (speedup 1.0000x reference)
#include <cuda_runtime.h>
#include <cuda_bf16.h>
#include <math.h>
#include <stdint.h>

#define BATCH   2
#define LSEQ    1024
#define DMODEL  2048
#define DINNER  4096
#define DSTATE  16
#define DTRANK  128
#define KCONV   4
#define MROWS   (BATCH*LSEQ)          // 2048
#define E2      (2*DINNER)            // 8192
#define XDBL_C  (DTRANK + 2*DSTATE)   // 160
#define NCHUNK  16
#define CLEN    (LSEQ/NCHUNK)         // 64
#define KSPLIT  8

// -------- fp32 scratch ------------------------------------------------------
__device__ __align__(16) float g_xz   [(size_t)MROWS * E2];
__device__ __align__(16) float g_xc   [(size_t)MROWS * DINNER];
__device__ __align__(16) float g_xdbl [(size_t)MROWS * XDBL_C];
__device__ __align__(16) float g_delta[(size_t)MROWS * DINNER];
__device__ __align__(16) float g_cA   [(size_t)BATCH*NCHUNK*DSTATE*DINNER];
__device__ __align__(16) float g_cS   [(size_t)BATCH*NCHUNK*DSTATE*DINNER];
__device__ __align__(16) float g_sini [(size_t)BATCH*NCHUNK*DSTATE*DINNER];
__device__ __align__(16) float g_part [(size_t)KSPLIT * MROWS * XDBL_C];

// -------- bf16 hi/lo planes -------------------------------------------------
__device__ __align__(16) __nv_bfloat16 g_hsH [(size_t)MROWS * DMODEL];
__device__ __align__(16) __nv_bfloat16 g_hsL [(size_t)MROWS * DMODEL];
__device__ __align__(16) __nv_bfloat16 g_winH[(size_t)E2 * DMODEL];
__device__ __align__(16) __nv_bfloat16 g_winL[(size_t)E2 * DMODEL];
__device__ __align__(16) __nv_bfloat16 g_xcH [(size_t)MROWS * DINNER];
__device__ __align__(16) __nv_bfloat16 g_xcL [(size_t)MROWS * DINNER];
__device__ __align__(16) __nv_bfloat16 g_wxH [(size_t)XDBL_C * DINNER];
__device__ __align__(16) __nv_bfloat16 g_wxL [(size_t)XDBL_C * DINNER];
__device__ __align__(16) __nv_bfloat16 g_dtH [(size_t)MROWS * DTRANK];
__device__ __align__(16) __nv_bfloat16 g_dtL [(size_t)MROWS * DTRANK];
__device__ __align__(16) __nv_bfloat16 g_wdtH[(size_t)DINNER * DTRANK];
__device__ __align__(16) __nv_bfloat16 g_wdtL[(size_t)DINNER * DTRANK];
__device__ __align__(16) __nv_bfloat16 g_yH  [(size_t)MROWS * DINNER];
__device__ __align__(16) __nv_bfloat16 g_yL  [(size_t)MROWS * DINNER];
__device__ __align__(16) __nv_bfloat16 g_woH [(size_t)DMODEL * DINNER];
__device__ __align__(16) __nv_bfloat16 g_woL [(size_t)DMODEL * DINNER];

// ======================= PTX helpers ========================================
__device__ __forceinline__ uint32_t smem_u32(const void* p) {
    uint32_t a;
    asm("{ .reg .u64 t; cvta.to.shared.u64 t, %1; cvt.u32.u64 %0, t; }"
        : "=r"(a) : "l"(p));
    return a;
}
__device__ __forceinline__ void cpa16(uint32_t dst, const void* src, uint32_t sz) {
    asm volatile("cp.async.cg.shared.global [%0], [%1], 16, %2;"
                 :: "r"(dst), "l"(src), "r"(sz) : "memory");
}
__device__ __forceinline__ void cpa_commit() {
    asm volatile("cp.async.commit_group;" ::: "memory");
}
__device__ __forceinline__ void cpa_wait2() {
    asm volatile("cp.async.wait_group 2;" ::: "memory");
}
__device__ __forceinline__ void ldsm4(uint32_t* r, uint32_t addr) {
    asm volatile("ldmatrix.sync.aligned.m8n8.x4.shared.b16 {%0,%1,%2,%3}, [%4];"
                 : "=r"(r[0]), "=r"(r[1]), "=r"(r[2]), "=r"(r[3]) : "r"(addr));
}
__device__ __forceinline__ void mma16(float* c, const uint32_t* a, const uint32_t* b) {
    asm volatile(
        "mma.sync.aligned.m16n8k16.row.col.f32.bf16.bf16.f32 "
        "{%0,%1,%2,%3}, {%4,%5,%6,%7}, {%8,%9}, {%0,%1,%2,%3};"
        : "+f"(c[0]), "+f"(c[1]), "+f"(c[2]), "+f"(c[3])
        : "r"(a[0]), "r"(a[1]), "r"(a[2]), "r"(a[3]), "r"(b[0]), "r"(b[1]));
}
// swizzled byte offset inside a (rows x 64B) plane
__device__ __forceinline__ uint32_t swf(int row, int ch) {
    return (uint32_t)(row * 64 + ((ch ^ ((row >> 1) & 3)) << 4));
}

// ============================================================================
// bf16 3-product NT GEMM:  C = AH.BH^T + AH.BL^T + AL.BH^T  ~= fp32 A.B^T
// CTA tile 128(M) x 256(N), BK=32, warp tile 64x64 (2x4 warps), 256 threads.
// Stage = {AH 8K, AL 8K, BH 16K, BL 16K} = 48 KB; 4-stage cp.async ring.
// 192 HMMA vs 32 LDSM per warp-chunk -> tensor-bound.
// EPI: 0 none, 1 softplus(v+bias), 2 v+bias.
// nsplit>1: blockIdx.z takes a K-range, writes partial slab z (EPI 0 only).
// Requires M%128==0, K%(32*nsplit)==0. N ragged ok.
// ============================================================================
#define STAGE_BYTES 49152u
#define G_SMEM      (4u * STAGE_BYTES)   // 192 KB

template<int EPI>
__global__ void __launch_bounds__(256, 1) bf_gemm(
    int M, int N, int K,
    const __nv_bfloat16* __restrict__ AH, const __nv_bfloat16* __restrict__ AL, int lda,
    const __nv_bfloat16* __restrict__ BH, const __nv_bfloat16* __restrict__ BL, int ldb,
    float* __restrict__ C, int ldc,
    const float* __restrict__ bias, int nsplit)
{
    extern __shared__ char smem[];
    const uint32_t sbase = smem_u32(smem);
    const int tid = threadIdx.x, lane = tid & 31, wid = tid >> 5;
    const int wm = wid >> 2, wn = wid & 3;           // warp grid 2(m) x 4(n)
    const int g = lane >> 2, tg = lane & 3;
    const int row0 = blockIdx.y * 128, col0 = blockIdx.x * 256;

    const int kper = K / nsplit;
    const int kbeg = blockIdx.z * kper;
    if (nsplit > 1) C += (size_t)blockIdx.z * M * ldc;
    const int nch = kper / 32;

    // ldmatrix lane geometry
    const int aro = (lane & 7) + ((lane >> 3) & 1) * 8;  // A row offset
    const int aco = lane >> 4;                            // A k-chunk offset
    const int bro = (lane & 7) + ((lane >> 4) << 3);      // B row offset
    const int bco = (lane >> 3) & 1;                      // B k-chunk offset

    float acc[4][8][4];
    #pragma unroll
    for (int i = 0; i < 4; i++)
        #pragma unroll
        for (int j = 0; j < 8; j++)
            #pragma unroll
            for (int q = 0; q < 4; q++) acc[i][j][q] = 0.f;

    auto issue = [&](int c) {
        if (c < nch) {
            const int koff = kbeg + c * 32;
            const uint32_t st = sbase + (uint32_t)(c & 3) * STAGE_BYTES;
            // A planes (128 rows)
            #pragma unroll
            for (int i = 0; i < 2; i++) {
                const int idx = tid + i * 256;
                const int row = idx >> 2, ch = idx & 3;
                const uint32_t sw = swf(row, ch);
                const size_t ga = (size_t)(row0 + row) * lda + koff + ch * 8;
                cpa16(st + sw,         AH + ga, 16u);
                cpa16(st + 8192u + sw, AL + ga, 16u);
            }
            // B planes (256 rows)
            #pragma unroll
            for (int i = 0; i < 4; i++) {
                const int idx = tid + i * 256;
                const int row = idx >> 2, ch = idx & 3;
                const uint32_t sw = swf(row, ch);
                const uint32_t szB = ((col0 + row) < N) ? 16u : 0u;
                const size_t gb = (size_t)(col0 + row) * ldb + koff + ch * 8;
                cpa16(st + 16384u + sw, BH + gb, szB);
                cpa16(st + 32768u + sw, BL + gb, szB);
            }
        }
        cpa_commit();
    };

    issue(0); issue(1); issue(2);

    for (int c = 0; c < nch; c++) {
        cpa_wait2();
        __syncthreads();
        issue(c + 3);

        const uint32_t sAH = sbase + (uint32_t)(c & 3) * STAGE_BYTES;
        const uint32_t sAL = sAH + 8192u;
        const uint32_t sBH = sAH + 16384u;
        const uint32_t sBL = sAH + 32768u;

        #pragma unroll
        for (int kk = 0; kk < 2; kk++) {
            uint32_t bb[16], ahc[16], aa[4];
            // B hi fragments (8 n-tiles)
            #pragma unroll
            for (int p = 0; p < 4; p++)
                ldsm4(&bb[p * 4], sBH + swf(wn * 64 + p * 16 + bro, 2 * kk + bco));
            // AH * BH (cache AH)
            #pragma unroll
            for (int mt = 0; mt < 4; mt++) {
                ldsm4(&ahc[mt * 4], sAH + swf(wm * 64 + mt * 16 + aro, 2 * kk + aco));
                #pragma unroll
                for (int nt = 0; nt < 8; nt++)
                    mma16(acc[mt][nt], &ahc[mt * 4], &bb[nt * 2]);
            }
            // AL * BH
            #pragma unroll
            for (int mt = 0; mt < 4; mt++) {
                ldsm4(aa, sAL + swf(wm * 64 + mt * 16 + aro, 2 * kk + aco));
                #pragma unroll
                for (int nt = 0; nt < 8; nt++)
                    mma16(acc[mt][nt], aa, &bb[nt * 2]);
            }
            // B lo fragments (reuse bb)
            #pragma unroll
            for (int p = 0; p < 4; p++)
                ldsm4(&bb[p * 4], sBL + swf(wn * 64 + p * 16 + bro, 2 * kk + bco));
            // AH(cached) * BL
            #pragma unroll
            for (int mt = 0; mt < 4; mt++)
                #pragma unroll
                for (int nt = 0; nt < 8; nt++)
                    mma16(acc[mt][nt], &ahc[mt * 4], &bb[nt * 2]);
        }
    }

    // epilogue
    #pragma unroll
    for (int mt = 0; mt < 4; mt++) {
        const int r = row0 + wm * 64 + mt * 16 + g;
        #pragma unroll
        for (int nt = 0; nt < 8; nt++) {
            const int c2 = col0 + wn * 64 + nt * 8 + 2 * tg;
            if (c2 < N) {
                float v0 = acc[mt][nt][0], v1 = acc[mt][nt][1];
                float v2 = acc[mt][nt][2], v3 = acc[mt][nt][3];
                if (EPI == 1) {
                    v0 += bias[c2]; v1 += bias[c2 + 1];
                    v2 += bias[c2]; v3 += bias[c2 + 1];
                    v0 = (v0 > 20.f) ? v0 : log1pf(__expf(v0));
                    v1 = (v1 > 20.f) ? v1 : log1pf(__expf(v1));
                    v2 = (v2 > 20.f) ? v2 : log1pf(__expf(v2));
                    v3 = (v3 > 20.f) ? v3 : log1pf(__expf(v3));
                } else if (EPI == 2) {
                    v0 += bias[c2]; v1 += bias[c2 + 1];
                    v2 += bias[c2]; v3 += bias[c2 + 1];
                }
                *(float2*)&C[(size_t)r * ldc + c2]       = make_float2(v0, v1);
                *(float2*)&C[(size_t)(r + 8) * ldc + c2] = make_float2(v2, v3);
            }
        }
    }
}

// ---------------------------------------------------------------------------
// merged hi/lo bf16 split over all 5 weight/activation tensors
// ---------------------------------------------------------------------------
struct SplitSeg { const float* src; __nv_bfloat16* hi; __nv_bfloat16* lo; int end; };
struct SplitTab { SplitSeg s[5]; };

__global__ void split_all(SplitTab tab, int total4)
{
    int i = blockIdx.x * 256 + threadIdx.x;
    if (i >= total4) return;
    int seg = 0, start = 0;
    #pragma unroll
    for (int t = 0; t < 4; t++)
        if (i >= tab.s[t].end) { seg = t + 1; start = tab.s[t].end; }
    const int li = i - start;
    const float4 v = ((const float4*)tab.s[seg].src)[li];
    __nv_bfloat162 h0, h1, l0, l1;
    h0.x = __float2bfloat16(v.x); l0.x = __float2bfloat16(v.x - __bfloat162float(h0.x));
    h0.y = __float2bfloat16(v.y); l0.y = __float2bfloat16(v.y - __bfloat162float(h0.y));
    h1.x = __float2bfloat16(v.z); l1.x = __float2bfloat16(v.z - __bfloat162float(h1.x));
    h1.y = __float2bfloat16(v.w); l1.y = __float2bfloat16(v.w - __bfloat162float(h1.y));
    ((__nv_bfloat162*)tab.s[seg].hi)[2*li]   = h0;
    ((__nv_bfloat162*)tab.s[seg].hi)[2*li+1] = h1;
    ((__nv_bfloat162*)tab.s[seg].lo)[2*li]   = l0;
    ((__nv_bfloat162*)tab.s[seg].lo)[2*li+1] = l1;
}

// split dt = g_xdbl[:, 0:128] (ld 160) -> compact 2048x128 planes
__global__ void split_dt_kernel()
{
    const int i = blockIdx.x * 256 + threadIdx.x;
    if (i >= MROWS * (DTRANK/4)) return;
    const int row = i >> 5, c4 = i & 31;
    const float4 v = *(const float4*)(g_xdbl + (size_t)row * XDBL_C + c4 * 4);
    __nv_bfloat162 h0, h1, l0, l1;
    h0.x = __float2bfloat16(v.x); l0.x = __float2bfloat16(v.x - __bfloat162float(h0.x));
    h0.y = __float2bfloat16(v.y); l0.y = __float2bfloat16(v.y - __bfloat162float(h0.y));
    h1.x = __float2bfloat16(v.z); l1.x = __float2bfloat16(v.z - __bfloat162float(h1.x));
    h1.y = __float2bfloat16(v.w); l1.y = __float2bfloat16(v.w - __bfloat162float(h1.y));
    const size_t o = (size_t)row * DTRANK + c4 * 4;
    *(__nv_bfloat162*)(g_dtH + o)     = h0; *(__nv_bfloat162*)(g_dtH + o + 2) = h1;
    *(__nv_bfloat162*)(g_dtL + o)     = l0; *(__nv_bfloat162*)(g_dtL + o + 2) = l1;
}

// deterministic split-K reduction
__global__ void reduce_splitk(int n)
{
    const int i = blockIdx.x * 256 + threadIdx.x;
    if (i < n) {
        float s = 0.f;
        #pragma unroll
        for (int z = 0; z < KSPLIT; z++) s += g_part[(size_t)z * n + i];
        g_xdbl[i] = s;
    }
}

// ---------------------------------------------------------------------------
// Depthwise causal conv (K=4) + SiLU, fused xc hi/lo split
// ---------------------------------------------------------------------------
__global__ void conv_silu_kernel(const float* __restrict__ conv_w,
                                 const float* __restrict__ conv_b)
{
    const int d  = blockIdx.x * 256 + threadIdx.x;
    const int b  = blockIdx.z;
    const int l0 = blockIdx.y * 128;

    const float w0 = conv_w[d*4+0], w1 = conv_w[d*4+1];
    const float w2 = conv_w[d*4+2], w3 = conv_w[d*4+3];
    const float cb = conv_b[d];

    const float* xb = g_xz + (size_t)b * LSEQ * E2 + d;
    const size_t ob = (size_t)b * LSEQ * DINNER + d;

    float x0 = (l0 >= 3) ? xb[(size_t)(l0-3) * E2] : 0.f;
    float x1 = (l0 >= 2) ? xb[(size_t)(l0-2) * E2] : 0.f;
    float x2 = (l0 >= 1) ? xb[(size_t)(l0-1) * E2] : 0.f;

    for (int l = l0; l < l0 + 128; l++) {
        float x3 = xb[(size_t)l * E2];
        float v  = fmaf(w0,x0, fmaf(w1,x1, fmaf(w2,x2, fmaf(w3,x3, cb))));
        float s  = 1.f / (1.f + __expf(-v));
        float o  = v * s;
        const size_t off = ob + (size_t)l * DINNER;
        g_xc[off] = o;
        __nv_bfloat16 h = __float2bfloat16(o);
        g_xcH[off] = h;
        g_xcL[off] = __float2bfloat16(o - __bfloat162float(h));
        x0 = x1; x1 = x2; x2 = x3;
    }
}

__global__ void conv_state_kernel(float* __restrict__ out)
{
    const int idx = blockIdx.x * 256 + threadIdx.x;
    const int b = idx >> 14;
    const int r = idx & 16383;
    const int d = r >> 2;
    const int k = r & 3;
    out[idx] = g_xz[((size_t)(b*LSEQ + (LSEQ - KCONV) + k)) * E2 + d];
}

// ---------------------------------------------------------------------------
// Chunked linear scan
// ---------------------------------------------------------------------------
__global__ void scan_phase1(const float* __restrict__ A_log)
{
    const int d = blockIdx.x * 256 + threadIdx.x;
    const int c = blockIdx.y, b = blockIdx.z;

    float a[DSTATE];
    #pragma unroll
    for (int n = 0; n < DSTATE; n++) a[n] = -__expf(A_log[d*DSTATE + n]);

    float s[DSTATE], ap[DSTATE];
    #pragma unroll
    for (int n = 0; n < DSTATE; n++) { s[n] = 0.f; ap[n] = 1.f; }

    const int mbase = b * LSEQ + c * CLEN;
    for (int t = 0; t < CLEN; t++) {
        const int m = mbase + t;
        const float dt = g_delta[(size_t)m * DINNER + d];
        const float u  = g_xc  [(size_t)m * DINNER + d];
        const float du = dt * u;
        const float* bp = g_xdbl + (size_t)m * XDBL_C + DTRANK;
        #pragma unroll
        for (int n = 0; n < DSTATE; n++) {
            float e = __expf(dt * a[n]);
            s[n]  = fmaf(e, s[n], du * __ldg(bp + n));
            ap[n] *= e;
        }
    }
    const size_t base = ((size_t)(b*NCHUNK + c) * DSTATE) * DINNER + d;
    #pragma unroll
    for (int n = 0; n < DSTATE; n++) {
        g_cA[base + (size_t)n * DINNER] = ap[n];
        g_cS[base + (size_t)n * DINNER] = s[n];
    }
}

__global__ void scan_phase2(float* __restrict__ last_state)
{
    const int d = blockIdx.x * 256 + threadIdx.x;
    const int n = blockIdx.y, b = blockIdx.z;
    float s = 0.f;
    #pragma unroll
    for (int c = 0; c < NCHUNK; c++) {
        const size_t off = ((size_t)(b*NCHUNK + c) * DSTATE + n) * DINNER + d;
        g_sini[off] = s;
        s = fmaf(g_cA[off], s, g_cS[off]);
    }
    last_state[((size_t)b * DINNER + d) * DSTATE + n] = s;
}

__global__ void scan_phase3(const float* __restrict__ A_log,
                            const float* __restrict__ Dvec)
{
    const int d = blockIdx.x * 256 + threadIdx.x;
    const int c = blockIdx.y, b = blockIdx.z;

    float a[DSTATE];
    #pragma unroll
    for (int n = 0; n < DSTATE; n++) a[n] = -__expf(A_log[d*DSTATE + n]);

    float s[DSTATE];
    const size_t base = ((size_t)(b*NCHUNK + c) * DSTATE) * DINNER + d;
    #pragma unroll
    for (int n = 0; n < DSTATE; n++) s[n] = g_sini[base + (size_t)n * DINNER];

    const float Dd = Dvec[d];
    const int mbase = b * LSEQ + c * CLEN;
    for (int t = 0; t < CLEN; t++) {
        const int m = mbase + t;
        const float dt = g_delta[(size_t)m * DINNER + d];
        const float u  = g_xc  [(size_t)m * DINNER + d];
        const float z  = g_xz  [(size_t)m * E2 + DINNER + d];
        const float du = dt * u;
        const float* bp = g_xdbl + (size_t)m * XDBL_C + DTRANK;
        const float* cp = bp + DSTATE;
        float yv = 0.f;
        #pragma unroll
        for (int n = 0; n < DSTATE; n++) {
            float e = __expf(dt * a[n]);
            s[n] = fmaf(e, s[n], du * __ldg(bp + n));
            yv   = fmaf(s[n], __ldg(cp + n), yv);
        }
        yv = fmaf(Dd, u, yv);
        const float sig = 1.f / (1.f + __expf(-z));
        const float yo  = yv * z * sig;
        const size_t off = (size_t)m * DINNER + d;
        __nv_bfloat16 h = __float2bfloat16(yo);
        g_yH[off] = h;
        g_yL[off] = __float2bfloat16(yo - __bfloat162float(h));
    }
}

// ---------------------------------------------------------------------------
extern "C" void kernel_launch(void* const* d_in, const int* in_sizes, int n_in,
                              void* d_out, int out_size)
{
    const float* hs     = (const float*)d_in[0];
    const float* W_in   = (const float*)d_in[1];
    const float* conv_w = (const float*)d_in[2];
    const float* conv_b = (const float*)d_in[3];
    const float* W_x    = (const float*)d_in[4];
    const float* W_dt   = (const float*)d_in[5];
    const float* b_dt   = (const float*)d_in[6];
    const float* A_log  = (const float*)d_in[7];
    const float* Dv     = (const float*)d_in[8];
    const float* W_out  = (const float*)d_in[9];
    const float* b_out  = (const float*)d_in[10];

    float* out        = (float*)d_out;
    float* conv_state = out + (size_t)BATCH * LSEQ * DMODEL;
    float* last_state = conv_state + (size_t)BATCH * DINNER * KCONV;

    float *p_xz, *p_xdbl, *p_delta, *p_part;
    cudaGetSymbolAddress((void**)&p_xz,    g_xz);
    cudaGetSymbolAddress((void**)&p_xdbl,  g_xdbl);
    cudaGetSymbolAddress((void**)&p_delta, g_delta);
    cudaGetSymbolAddress((void**)&p_part,  g_part);

    __nv_bfloat16 *hsH,*hsL,*winH,*winL,*xcH,*xcL,*wxH,*wxL,*dtH,*dtL,*wdtH,*wdtL,*yH,*yL,*woH,*woL;
    cudaGetSymbolAddress((void**)&hsH, g_hsH);   cudaGetSymbolAddress((void**)&hsL, g_hsL);
    cudaGetSymbolAddress((void**)&winH, g_winH); cudaGetSymbolAddress((void**)&winL, g_winL);
    cudaGetSymbolAddress((void**)&xcH, g_xcH);   cudaGetSymbolAddress((void**)&xcL, g_xcL);
    cudaGetSymbolAddress((void**)&wxH, g_wxH);   cudaGetSymbolAddress((void**)&wxL, g_wxL);
    cudaGetSymbolAddress((void**)&dtH, g_dtH);   cudaGetSymbolAddress((void**)&dtL, g_dtL);
    cudaGetSymbolAddress((void**)&wdtH, g_wdtH); cudaGetSymbolAddress((void**)&wdtL, g_wdtL);
    cudaGetSymbolAddress((void**)&yH, g_yH);     cudaGetSymbolAddress((void**)&yL, g_yL);
    cudaGetSymbolAddress((void**)&woH, g_woH);   cudaGetSymbolAddress((void**)&woL, g_woL);

    cudaFuncSetAttribute(bf_gemm<0>, cudaFuncAttributeMaxDynamicSharedMemorySize, G_SMEM);
    cudaFuncSetAttribute(bf_gemm<1>, cudaFuncAttributeMaxDynamicSharedMemorySize, G_SMEM);
    cudaFuncSetAttribute(bf_gemm<2>, cudaFuncAttributeMaxDynamicSharedMemorySize, G_SMEM);

    // 0) merged hi/lo splits of pure inputs
    {
        SplitTab tab;
        int e0 = MROWS*DMODEL/4;
        int e1 = e0 + E2*DMODEL/4;
        int e2 = e1 + XDBL_C*DINNER/4;
        int e3 = e2 + DINNER*DTRANK/4;
        int e4 = e3 + DMODEL*DINNER/4;
        tab.s[0] = { hs,    hsH,  hsL,  e0 };
        tab.s[1] = { W_in,  winH, winL, e1 };
        tab.s[2] = { W_x,   wxH,  wxL,  e2 };
        tab.s[3] = { W_dt,  wdtH, wdtL, e3 };
        tab.s[4] = { W_out, woH,  woL,  e4 };
        split_all<<<(e4 + 255)/256, 256>>>(tab, e4);
    }

    // 1) xz[m][e] = hs[m,:] . W_in[e,:]      (2048 x 8192 x 2048)
    bf_gemm<0><<<dim3(E2/256, MROWS/128), 256, G_SMEM>>>(
        MROWS, E2, DMODEL, hsH, hsL, DMODEL, winH, winL, DMODEL, p_xz, E2, nullptr, 1);

    // 2) depthwise conv + SiLU (fused xc split); conv_state
    conv_silu_kernel<<<dim3(DINNER/256, LSEQ/128, BATCH), 256>>>(conv_w, conv_b);
    conv_state_kernel<<<dim3((BATCH*DINNER*KCONV)/256), 256>>>(conv_state);

    // 3) x_dbl[m][e] = xc[m,:] . W_x[e,:]    (2048 x 160 x 4096) split-K=8
    bf_gemm<0><<<dim3(1, MROWS/128, KSPLIT), 256, G_SMEM>>>(
        MROWS, XDBL_C, DINNER, xcH, xcL, DINNER, wxH, wxL, DINNER, p_part, XDBL_C, nullptr, KSPLIT);
    reduce_splitk<<<(MROWS*XDBL_C + 255)/256, 256>>>(MROWS * XDBL_C);
    split_dt_kernel<<<(MROWS*(DTRANK/4) + 255)/256, 256>>>();

    // 4) delta[m][d] = softplus(dt[m,:] . W_dt[d,:] + b_dt[d])   (2048 x 4096 x 128)
    bf_gemm<1><<<dim3(DINNER/256, MROWS/128), 256, G_SMEM>>>(
        MROWS, DINNER, DTRANK, dtH, dtL, DTRANK, wdtH, wdtL, DTRANK, p_delta, DINNER, b_dt, 1);

    // 5) chunked selective scan (+ gating, fused y split), emits last_state
    scan_phase1<<<dim3(DINNER/256, NCHUNK, BATCH), 256>>>(A_log);
    scan_phase2<<<dim3(DINNER/256, DSTATE, BATCH), 256>>>(last_state);
    scan_phase3<<<dim3(DINNER/256, NCHUNK, BATCH), 256>>>(A_log, Dv);

    // 6) out[m][e] = y[m,:] . W_out[e,:] + b_out[e]   (2048 x 2048 x 4096)
    bf_gemm<2><<<dim3(DMODEL/256, MROWS/128), 256, G_SMEM>>>(
        MROWS, DMODEL, DINNER, yH, yL, DINNER, woH, woL, DINNER, out, DMODEL, b_out, 1);
}

// round 7
// speedup vs baseline: 1.3739x; 1.3739x over previous
#include <cuda_runtime.h>
#include <cuda_fp16.h>
#include <math.h>
#include <stdint.h>

#define BATCH   2
#define LSEQ    1024
#define DMODEL  2048
#define DINNER  4096
#define DSTATE  16
#define DTRANK  128
#define KCONV   4
#define MROWS   (BATCH*LSEQ)          // 2048
#define E2      (2*DINNER)            // 8192
#define XDBL_C  (DTRANK + 2*DSTATE)   // 160
#define NCHUNK  16
#define CLEN    (LSEQ/NCHUNK)         // 64
#define KSPLIT  8

// -------- fp32 scratch ------------------------------------------------------
__device__ __align__(16) float g_xz   [(size_t)MROWS * E2];
__device__ __align__(16) float g_xc   [(size_t)MROWS * DINNER];
__device__ __align__(16) float g_xdbl [(size_t)MROWS * XDBL_C];
__device__ __align__(16) float g_delta[(size_t)MROWS * DINNER];
__device__ __align__(16) float g_cA   [(size_t)BATCH*NCHUNK*DSTATE*DINNER];
__device__ __align__(16) float g_cS   [(size_t)BATCH*NCHUNK*DSTATE*DINNER];
__device__ __align__(16) float g_sini [(size_t)BATCH*NCHUNK*DSTATE*DINNER];
__device__ __align__(16) float g_part [(size_t)KSPLIT * MROWS * XDBL_C];

// -------- fp16 planes: activations hi+lo, weights hi only --------------------
__device__ __align__(16) __half g_hsH [(size_t)MROWS * DMODEL];
__device__ __align__(16) __half g_hsL [(size_t)MROWS * DMODEL];
__device__ __align__(16) __half g_winH[(size_t)E2 * DMODEL];
__device__ __align__(16) __half g_xcH [(size_t)MROWS * DINNER];
__device__ __align__(16) __half g_xcL [(size_t)MROWS * DINNER];
__device__ __align__(16) __half g_wxH [(size_t)XDBL_C * DINNER];
__device__ __align__(16) __half g_dtH [(size_t)MROWS * DTRANK];
__device__ __align__(16) __half g_dtL [(size_t)MROWS * DTRANK];
__device__ __align__(16) __half g_wdtH[(size_t)DINNER * DTRANK];
__device__ __align__(16) __half g_yH  [(size_t)MROWS * DINNER];
__device__ __align__(16) __half g_yL  [(size_t)MROWS * DINNER];
__device__ __align__(16) __half g_woH [(size_t)DMODEL * DINNER];

// ======================= PTX helpers ========================================
__device__ __forceinline__ uint32_t smem_u32(const void* p) {
    uint32_t a;
    asm("{ .reg .u64 t; cvta.to.shared.u64 t, %1; cvt.u32.u64 %0, t; }"
        : "=r"(a) : "l"(p));
    return a;
}
__device__ __forceinline__ void cpa16(uint32_t dst, const void* src, uint32_t sz) {
    asm volatile("cp.async.cg.shared.global [%0], [%1], 16, %2;"
                 :: "r"(dst), "l"(src), "r"(sz) : "memory");
}
__device__ __forceinline__ void cpa_commit() {
    asm volatile("cp.async.commit_group;" ::: "memory");
}
__device__ __forceinline__ void cpa_wait1() {
    asm volatile("cp.async.wait_group 1;" ::: "memory");
}
__device__ __forceinline__ void ldsm4(uint32_t* r, uint32_t addr) {
    asm volatile("ldmatrix.sync.aligned.m8n8.x4.shared.b16 {%0,%1,%2,%3}, [%4];"
                 : "=r"(r[0]), "=r"(r[1]), "=r"(r[2]), "=r"(r[3]) : "r"(addr));
}
__device__ __forceinline__ void mma16(float* c, const uint32_t* a, const uint32_t* b) {
    asm volatile(
        "mma.sync.aligned.m16n8k16.row.col.f32.f16.f16.f32 "
        "{%0,%1,%2,%3}, {%4,%5,%6,%7}, {%8,%9}, {%0,%1,%2,%3};"
        : "+f"(c[0]), "+f"(c[1]), "+f"(c[2]), "+f"(c[3])
        : "r"(a[0]), "r"(a[1]), "r"(a[2]), "r"(a[3]), "r"(b[0]), "r"(b[1]));
}
// swizzled byte offset inside a (rows x 64B) plane
__device__ __forceinline__ uint32_t swf(int row, int ch) {
    return (uint32_t)(row * 64 + ((ch ^ ((row >> 1) & 3)) << 4));
}

// ============================================================================
// fp16 2-product NT GEMM:  C = AH.BH^T + AL.BH^T  ~= fp32 A.B^T
//   (A split hi/lo in fp16, B truncated to fp16; error ~2.8e-4 RMS)
// CTA tile 128x128, BK=32, 8 warps (warp tile 64x32), 2 CTA/SM.
// Stage = {AH 8K, AL 8K, BH 8K} = 24 KB; 3-stage cp.async ring.
// EPI: 0 none, 1 softplus(v+bias), 2 v+bias.
// nsplit>1: blockIdx.z takes a K-range, writes partial slab z (EPI 0 only).
// Requires M%128==0, K%(32*nsplit)==0. N ragged ok.
// ============================================================================
#define STAGE_BYTES 24576u
#define G_SMEM      (3u * STAGE_BYTES)   // 72 KB

template<int EPI>
__global__ void __launch_bounds__(256, 2) hf_gemm(
    int M, int N, int K,
    const __half* __restrict__ AH, const __half* __restrict__ AL, int lda,
    const __half* __restrict__ BH, int ldb,
    float* __restrict__ C, int ldc,
    const float* __restrict__ bias, int nsplit)
{
    extern __shared__ char smem[];
    const uint32_t sbase = smem_u32(smem);
    const int tid = threadIdx.x, lane = tid & 31, wid = tid >> 5;
    const int wm = wid >> 2, wn = wid & 3;           // warp grid 2(m) x 4(n)
    const int g = lane >> 2, tg = lane & 3;
    const int row0 = blockIdx.y * 128, col0 = blockIdx.x * 128;

    const int kper = K / nsplit;
    const int kbeg = blockIdx.z * kper;
    if (nsplit > 1) C += (size_t)blockIdx.z * M * ldc;
    const int nch = kper / 32;

    // ldmatrix lane geometry
    const int aro = (lane & 7) + ((lane >> 3) & 1) * 8;  // A row offset
    const int aco = lane >> 4;                            // A k-chunk offset
    const int bro = (lane & 7) + ((lane >> 4) << 3);      // B row offset
    const int bco = (lane >> 3) & 1;                      // B k-chunk offset

    float acc[4][4][4];
    #pragma unroll
    for (int i = 0; i < 4; i++)
        #pragma unroll
        for (int j = 0; j < 4; j++)
            #pragma unroll
            for (int q = 0; q < 4; q++) acc[i][j][q] = 0.f;

    auto issue = [&](int c) {
        if (c < nch) {
            const int koff = kbeg + c * 32;
            const uint32_t st = sbase + (uint32_t)(c % 3) * STAGE_BYTES;
            #pragma unroll
            for (int i = 0; i < 2; i++) {
                const int idx = tid + i * 256;
                const int row = idx >> 2, ch = idx & 3;
                const uint32_t sw = swf(row, ch);
                const size_t ga = (size_t)(row0 + row) * lda + koff + ch * 8;
                cpa16(st + sw,         AH + ga, 16u);
                cpa16(st + 8192u + sw, AL + ga, 16u);
                const uint32_t szB = ((col0 + row) < N) ? 16u : 0u;
                const size_t gb = (size_t)(col0 + row) * ldb + koff + ch * 8;
                cpa16(st + 16384u + sw, BH + gb, szB);
            }
        }
        cpa_commit();
    };

    issue(0);
    issue(1);

    for (int c = 0; c < nch; c++) {
        cpa_wait1();
        __syncthreads();
        issue(c + 2);

        const uint32_t sAH = sbase + (uint32_t)(c % 3) * STAGE_BYTES;
        const uint32_t sAL = sAH + 8192u;
        const uint32_t sBH = sAH + 16384u;

        #pragma unroll
        for (int kk = 0; kk < 2; kk++) {
            uint32_t bb[8], aa[4];
            // B hi fragments (4 n-tiles)
            #pragma unroll
            for (int p = 0; p < 2; p++)
                ldsm4(&bb[p * 4], sBH + swf(wn * 32 + p * 16 + bro, 2 * kk + bco));
            // AH * BH
            #pragma unroll
            for (int mt = 0; mt < 4; mt++) {
                ldsm4(aa, sAH + swf(wm * 64 + mt * 16 + aro, 2 * kk + aco));
                mma16(acc[mt][0], aa, &bb[0]); mma16(acc[mt][1], aa, &bb[2]);
                mma16(acc[mt][2], aa, &bb[4]); mma16(acc[mt][3], aa, &bb[6]);
            }
            // AL * BH
            #pragma unroll
            for (int mt = 0; mt < 4; mt++) {
                ldsm4(aa, sAL + swf(wm * 64 + mt * 16 + aro, 2 * kk + aco));
                mma16(acc[mt][0], aa, &bb[0]); mma16(acc[mt][1], aa, &bb[2]);
                mma16(acc[mt][2], aa, &bb[4]); mma16(acc[mt][3], aa, &bb[6]);
            }
        }
    }

    // epilogue
    #pragma unroll
    for (int mt = 0; mt < 4; mt++) {
        const int r = row0 + wm * 64 + mt * 16 + g;
        #pragma unroll
        for (int nt = 0; nt < 4; nt++) {
            const int c2 = col0 + wn * 32 + nt * 8 + 2 * tg;
            if (c2 < N) {
                float v0 = acc[mt][nt][0], v1 = acc[mt][nt][1];
                float v2 = acc[mt][nt][2], v3 = acc[mt][nt][3];
                if (EPI == 1) {
                    v0 += bias[c2]; v1 += bias[c2 + 1];
                    v2 += bias[c2]; v3 += bias[c2 + 1];
                    v0 = (v0 > 20.f) ? v0 : log1pf(__expf(v0));
                    v1 = (v1 > 20.f) ? v1 : log1pf(__expf(v1));
                    v2 = (v2 > 20.f) ? v2 : log1pf(__expf(v2));
                    v3 = (v3 > 20.f) ? v3 : log1pf(__expf(v3));
                } else if (EPI == 2) {
                    v0 += bias[c2]; v1 += bias[c2 + 1];
                    v2 += bias[c2]; v3 += bias[c2 + 1];
                }
                *(float2*)&C[(size_t)r * ldc + c2]       = make_float2(v0, v1);
                *(float2*)&C[(size_t)(r + 8) * ldc + c2] = make_float2(v2, v3);
            }
        }
    }
}

// ---------------------------------------------------------------------------
// merged fp16 split: activations hi+lo, weights hi only (lo == nullptr)
// ---------------------------------------------------------------------------
struct SplitSeg { const float* src; __half* hi; __half* lo; int end; };
struct SplitTab { SplitSeg s[5]; };

__global__ void split_all(SplitTab tab, int total4)
{
    int i = blockIdx.x * 256 + threadIdx.x;
    if (i >= total4) return;
    int seg = 0, start = 0;
    #pragma unroll
    for (int t = 0; t < 4; t++)
        if (i >= tab.s[t].end) { seg = t + 1; start = tab.s[t].end; }
    const int li = i - start;
    const float4 v = ((const float4*)tab.s[seg].src)[li];
    __half2 h0, h1;
    h0.x = __float2half_rn(v.x); h0.y = __float2half_rn(v.y);
    h1.x = __float2half_rn(v.z); h1.y = __float2half_rn(v.w);
    ((__half2*)tab.s[seg].hi)[2*li]   = h0;
    ((__half2*)tab.s[seg].hi)[2*li+1] = h1;
    if (tab.s[seg].lo) {
        __half2 l0, l1;
        l0.x = __float2half_rn(v.x - __half2float(h0.x));
        l0.y = __float2half_rn(v.y - __half2float(h0.y));
        l1.x = __float2half_rn(v.z - __half2float(h1.x));
        l1.y = __float2half_rn(v.w - __half2float(h1.y));
        ((__half2*)tab.s[seg].lo)[2*li]   = l0;
        ((__half2*)tab.s[seg].lo)[2*li+1] = l1;
    }
}

// split dt = g_xdbl[:, 0:128] (ld 160) -> compact 2048x128 hi/lo planes
__global__ void split_dt_kernel()
{
    const int i = blockIdx.x * 256 + threadIdx.x;
    if (i >= MROWS * (DTRANK/4)) return;
    const int row = i >> 5, c4 = i & 31;
    const float4 v = *(const float4*)(g_xdbl + (size_t)row * XDBL_C + c4 * 4);
    __half2 h0, h1, l0, l1;
    h0.x = __float2half_rn(v.x); l0.x = __float2half_rn(v.x - __half2float(h0.x));
    h0.y = __float2half_rn(v.y); l0.y = __float2half_rn(v.y - __half2float(h0.y));
    h1.x = __float2half_rn(v.z); l1.x = __float2half_rn(v.z - __half2float(h1.x));
    h1.y = __float2half_rn(v.w); l1.y = __float2half_rn(v.w - __half2float(h1.y));
    const size_t o = (size_t)row * DTRANK + c4 * 4;
    *(__half2*)(g_dtH + o)     = h0; *(__half2*)(g_dtH + o + 2) = h1;
    *(__half2*)(g_dtL + o)     = l0; *(__half2*)(g_dtL + o + 2) = l1;
}

// deterministic split-K reduction
__global__ void reduce_splitk(int n)
{
    const int i = blockIdx.x * 256 + threadIdx.x;
    if (i < n) {
        float s = 0.f;
        #pragma unroll
        for (int z = 0; z < KSPLIT; z++) s += g_part[(size_t)z * n + i];
        g_xdbl[i] = s;
    }
}

// ---------------------------------------------------------------------------
// Depthwise causal conv (K=4) + SiLU, fused xc fp16 hi/lo split
// ---------------------------------------------------------------------------
__global__ void conv_silu_kernel(const float* __restrict__ conv_w,
                                 const float* __restrict__ conv_b)
{
    const int d  = blockIdx.x * 256 + threadIdx.x;
    const int b  = blockIdx.z;
    const int l0 = blockIdx.y * 128;

    const float w0 = conv_w[d*4+0], w1 = conv_w[d*4+1];
    const float w2 = conv_w[d*4+2], w3 = conv_w[d*4+3];
    const float cb = conv_b[d];

    const float* xb = g_xz + (size_t)b * LSEQ * E2 + d;
    const size_t ob = (size_t)b * LSEQ * DINNER + d;

    float x0 = (l0 >= 3) ? xb[(size_t)(l0-3) * E2] : 0.f;
    float x1 = (l0 >= 2) ? xb[(size_t)(l0-2) * E2] : 0.f;
    float x2 = (l0 >= 1) ? xb[(size_t)(l0-1) * E2] : 0.f;

    for (int l = l0; l < l0 + 128; l++) {
        float x3 = xb[(size_t)l * E2];
        float v  = fmaf(w0,x0, fmaf(w1,x1, fmaf(w2,x2, fmaf(w3,x3, cb))));
        float s  = 1.f / (1.f + __expf(-v));
        float o  = v * s;
        const size_t off = ob + (size_t)l * DINNER;
        g_xc[off] = o;
        __half h = __float2half_rn(o);
        g_xcH[off] = h;
        g_xcL[off] = __float2half_rn(o - __half2float(h));
        x0 = x1; x1 = x2; x2 = x3;
    }
}

__global__ void conv_state_kernel(float* __restrict__ out)
{
    const int idx = blockIdx.x * 256 + threadIdx.x;
    const int b = idx >> 14;
    const int r = idx & 16383;
    const int d = r >> 2;
    const int k = r & 3;
    out[idx] = g_xz[((size_t)(b*LSEQ + (LSEQ - KCONV) + k)) * E2 + d];
}

// ---------------------------------------------------------------------------
// Chunked linear scan
// ---------------------------------------------------------------------------
__global__ void scan_phase1(const float* __restrict__ A_log)
{
    const int d = blockIdx.x * 256 + threadIdx.x;
    const int c = blockIdx.y, b = blockIdx.z;

    float a[DSTATE];
    #pragma unroll
    for (int n = 0; n < DSTATE; n++) a[n] = -__expf(A_log[d*DSTATE + n]);

    float s[DSTATE], ap[DSTATE];
    #pragma unroll
    for (int n = 0; n < DSTATE; n++) { s[n] = 0.f; ap[n] = 1.f; }

    const int mbase = b * LSEQ + c * CLEN;
    for (int t = 0; t < CLEN; t++) {
        const int m = mbase + t;
        const float dt = g_delta[(size_t)m * DINNER + d];
        const float u  = g_xc  [(size_t)m * DINNER + d];
        const float du = dt * u;
        const float* bp = g_xdbl + (size_t)m * XDBL_C + DTRANK;
        #pragma unroll
        for (int n = 0; n < DSTATE; n++) {
            float e = __expf(dt * a[n]);
            s[n]  = fmaf(e, s[n], du * __ldg(bp + n));
            ap[n] *= e;
        }
    }
    const size_t base = ((size_t)(b*NCHUNK + c) * DSTATE) * DINNER + d;
    #pragma unroll
    for (int n = 0; n < DSTATE; n++) {
        g_cA[base + (size_t)n * DINNER] = ap[n];
        g_cS[base + (size_t)n * DINNER] = s[n];
    }
}

__global__ void scan_phase2(float* __restrict__ last_state)
{
    const int d = blockIdx.x * 256 + threadIdx.x;
    const int n = blockIdx.y, b = blockIdx.z;
    float s = 0.f;
    #pragma unroll
    for (int c = 0; c < NCHUNK; c++) {
        const size_t off = ((size_t)(b*NCHUNK + c) * DSTATE + n) * DINNER + d;
        g_sini[off] = s;
        s = fmaf(g_cA[off], s, g_cS[off]);
    }
    last_state[((size_t)b * DINNER + d) * DSTATE + n] = s;
}

__global__ void scan_phase3(const float* __restrict__ A_log,
                            const float* __restrict__ Dvec)
{
    const int d = blockIdx.x * 256 + threadIdx.x;
    const int c = blockIdx.y, b = blockIdx.z;

    float a[DSTATE];
    #pragma unroll
    for (int n = 0; n < DSTATE; n++) a[n] = -__expf(A_log[d*DSTATE + n]);

    float s[DSTATE];
    const size_t base = ((size_t)(b*NCHUNK + c) * DSTATE) * DINNER + d;
    #pragma unroll
    for (int n = 0; n < DSTATE; n++) s[n] = g_sini[base + (size_t)n * DINNER];

    const float Dd = Dvec[d];
    const int mbase = b * LSEQ + c * CLEN;
    for (int t = 0; t < CLEN; t++) {
        const int m = mbase + t;
        const float dt = g_delta[(size_t)m * DINNER + d];
        const float u  = g_xc  [(size_t)m * DINNER + d];
        const float z  = g_xz  [(size_t)m * E2 + DINNER + d];
        const float du = dt * u;
        const float* bp = g_xdbl + (size_t)m * XDBL_C + DTRANK;
        const float* cp = bp + DSTATE;
        float yv = 0.f;
        #pragma unroll
        for (int n = 0; n < DSTATE; n++) {
            float e = __expf(dt * a[n]);
            s[n] = fmaf(e, s[n], du * __ldg(bp + n));
            yv   = fmaf(s[n], __ldg(cp + n), yv);
        }
        yv = fmaf(Dd, u, yv);
        const float sig = 1.f / (1.f + __expf(-z));
        const float yo  = yv * z * sig;
        const size_t off = (size_t)m * DINNER + d;
        __half h = __float2half_rn(yo);
        g_yH[off] = h;
        g_yL[off] = __float2half_rn(yo - __half2float(h));
    }
}

// ---------------------------------------------------------------------------
extern "C" void kernel_launch(void* const* d_in, const int* in_sizes, int n_in,
                              void* d_out, int out_size)
{
    const float* hs     = (const float*)d_in[0];
    const float* W_in   = (const float*)d_in[1];
    const float* conv_w = (const float*)d_in[2];
    const float* conv_b = (const float*)d_in[3];
    const float* W_x    = (const float*)d_in[4];
    const float* W_dt   = (const float*)d_in[5];
    const float* b_dt   = (const float*)d_in[6];
    const float* A_log  = (const float*)d_in[7];
    const float* Dv     = (const float*)d_in[8];
    const float* W_out  = (const float*)d_in[9];
    const float* b_out  = (const float*)d_in[10];

    float* out        = (float*)d_out;
    float* conv_state = out + (size_t)BATCH * LSEQ * DMODEL;
    float* last_state = conv_state + (size_t)BATCH * DINNER * KCONV;

    float *p_xz, *p_xdbl, *p_delta, *p_part;
    cudaGetSymbolAddress((void**)&p_xz,    g_xz);
    cudaGetSymbolAddress((void**)&p_xdbl,  g_xdbl);
    cudaGetSymbolAddress((void**)&p_delta, g_delta);
    cudaGetSymbolAddress((void**)&p_part,  g_part);

    __half *hsH,*hsL,*winH,*xcH,*xcL,*wxH,*dtH,*dtL,*wdtH,*yH,*yL,*woH;
    cudaGetSymbolAddress((void**)&hsH, g_hsH);   cudaGetSymbolAddress((void**)&hsL, g_hsL);
    cudaGetSymbolAddress((void**)&winH, g_winH);
    cudaGetSymbolAddress((void**)&xcH, g_xcH);   cudaGetSymbolAddress((void**)&xcL, g_xcL);
    cudaGetSymbolAddress((void**)&wxH, g_wxH);
    cudaGetSymbolAddress((void**)&dtH, g_dtH);   cudaGetSymbolAddress((void**)&dtL, g_dtL);
    cudaGetSymbolAddress((void**)&wdtH, g_wdtH);
    cudaGetSymbolAddress((void**)&yH, g_yH);     cudaGetSymbolAddress((void**)&yL, g_yL);
    cudaGetSymbolAddress((void**)&woH, g_woH);

    cudaFuncSetAttribute(hf_gemm<0>, cudaFuncAttributeMaxDynamicSharedMemorySize, G_SMEM);
    cudaFuncSetAttribute(hf_gemm<1>, cudaFuncAttributeMaxDynamicSharedMemorySize, G_SMEM);
    cudaFuncSetAttribute(hf_gemm<2>, cudaFuncAttributeMaxDynamicSharedMemorySize, G_SMEM);

    // 0) merged fp16 splits (hs: hi+lo; weights: hi only)
    {
        SplitTab tab;
        int e0 = MROWS*DMODEL/4;
        int e1 = e0 + E2*DMODEL/4;
        int e2 = e1 + XDBL_C*DINNER/4;
        int e3 = e2 + DINNER*DTRANK/4;
        int e4 = e3 + DMODEL*DINNER/4;
        tab.s[0] = { hs,    hsH,  hsL,    e0 };
        tab.s[1] = { W_in,  winH, nullptr, e1 };
        tab.s[2] = { W_x,   wxH,  nullptr, e2 };
        tab.s[3] = { W_dt,  wdtH, nullptr, e3 };
        tab.s[4] = { W_out, woH,  nullptr, e4 };
        split_all<<<(e4 + 255)/256, 256>>>(tab, e4);
    }

    // 1) xz[m][e] = hs[m,:] . W_in[e,:]      (2048 x 8192 x 2048)
    hf_gemm<0><<<dim3(E2/128, MROWS/128), 256, G_SMEM>>>(
        MROWS, E2, DMODEL, hsH, hsL, DMODEL, winH, DMODEL, p_xz, E2, nullptr, 1);

    // 2) depthwise conv + SiLU (fused xc split); conv_state
    conv_silu_kernel<<<dim3(DINNER/256, LSEQ/128, BATCH), 256>>>(conv_w, conv_b);
    conv_state_kernel<<<dim3((BATCH*DINNER*KCONV)/256), 256>>>(conv_state);

    // 3) x_dbl[m][e] = xc[m,:] . W_x[e,:]    (2048 x 160 x 4096) split-K=8
    hf_gemm<0><<<dim3(2, MROWS/128, KSPLIT), 256, G_SMEM>>>(
        MROWS, XDBL_C, DINNER, xcH, xcL, DINNER, wxH, DINNER, p_part, XDBL_C, nullptr, KSPLIT);
    reduce_splitk<<<(MROWS*XDBL_C + 255)/256, 256>>>(MROWS * XDBL_C);
    split_dt_kernel<<<(MROWS*(DTRANK/4) + 255)/256, 256>>>();

    // 4) delta[m][d] = softplus(dt[m,:] . W_dt[d,:] + b_dt[d])   (2048 x 4096 x 128)
    hf_gemm<1><<<dim3(DINNER/128, MROWS/128), 256, G_SMEM>>>(
        MROWS, DINNER, DTRANK, dtH, dtL, DTRANK, wdtH, DTRANK, p_delta, DINNER, b_dt, 1);

    // 5) chunked selective scan (+ gating, fused y split), emits last_state
    scan_phase1<<<dim3(DINNER/256, NCHUNK, BATCH), 256>>>(A_log);
    scan_phase2<<<dim3(DINNER/256, DSTATE, BATCH), 256>>>(last_state);
    scan_phase3<<<dim3(DINNER/256, NCHUNK, BATCH), 256>>>(A_log, Dv);

    // 6) out[m][e] = y[m,:] . W_out[e,:] + b_out[e]   (2048 x 2048 x 4096)
    hf_gemm<2><<<dim3(DMODEL/128, MROWS/128), 256, G_SMEM>>>(
        MROWS, DMODEL, DINNER, yH, yL, DINNER, woH, DINNER, out, DMODEL, b_out, 1);
}